// round 15
// baseline (speedup 1.0000x reference)
#include <cuda_runtime.h>
#include <cuda_fp16.h>
#include <mma.h>
#include <math.h>

using namespace nvcuda;

#define NEXP 8
#define NB   1024
#define NA   32
#define DTOK 128
#define FF   1024
#define HH   512
#define NRW  4
#define MAXG 520
#define NT   256

// ---------------- scratch (weights fp16, transposed) ----------------
__device__ __half g_win_h [NEXP*DTOK*384];
__device__ __half g_wout_h[NEXP*DTOK*DTOK];
__device__ __half g_w1_h  [NEXP*DTOK*FF];
__device__ __half g_w2_h  [NEXP*FF*DTOK];
__device__ __half g_h1_h  [4096*HH];

__device__ float  g_scr   [(size_t)MAXG*128*384];
__device__ float  g_ys    [2u*NB*4096];
__device__ float4 g_assign[NB];
__device__ float  g_lse   [NB];
__device__ float  g_hid   [NB*HH];
__device__ int    g_el_bs [NEXP*2048];
__device__ float  g_el_g  [NEXP*2048];
__device__ int4   g_grp   [MAXG];

// ---------------- expert smem (bytes), total 106496 -> 2 blocks/SM ----------------
#define OFF_AH   0          // 128x136 half (34816)
#define OFF_B0   34816      // 18432
#define OFF_B1   53248      // 18432  (SC scores alias over B0+B1: 33792 B)
#define OFF_A2H  71680      // 128x72 half (18432); CB (128x68 fp32 = 34816) aliases 71680..106496
#define SMEM_BYTES 106496

// ---------------- head1 smem ----------------
#define H1_XH    0          // 32x72 half (4608)
#define H1_WH    4608       // 64x136 half (17408); OB (32x132 fp32 = 16896) alias
#define H1_SMEM  (4608 + 17408)

typedef wmma::fragment<wmma::matrix_a, 16,16,16, __half, wmma::row_major> HA;
typedef wmma::fragment<wmma::matrix_b, 16,16,16, __half, wmma::row_major> HB;
typedef wmma::fragment<wmma::accumulator, 16,16,16, float> HC;

__device__ __forceinline__ void cpa16(void* dst, const void* src) {
    unsigned d = (unsigned)__cvta_generic_to_shared(dst);
    asm volatile("cp.async.cg.shared.global [%0], [%1], 16;\n" :: "r"(d), "l"(src));
}
#define CP_COMMIT() asm volatile("cp.async.commit_group;\n" ::: "memory")
#define CP_WAIT0()  asm volatile("cp.async.wait_group 0;\n" ::: "memory")
#define CP_WAIT1()  asm volatile("cp.async.wait_group 1;\n" ::: "memory")

// ---------------- repack (transposed, fp16) ----------------
__global__ void repack_kernel(const float* __restrict__ w_in,
                              const float* __restrict__ w_out,
                              const float* __restrict__ w1,
                              const float* __restrict__ w2,
                              const float* __restrict__ hw1) {
    const int N_in  = NEXP*384*DTOK;
    const int N_out = NEXP*DTOK*DTOK;
    const int N_w1  = NEXP*FF*DTOK;
    const int N_w2  = NEXP*DTOK*FF;
    const int N_h1  = HH*4096;
    const int total = N_in + N_out + N_w1 + N_w2 + N_h1;
    for (int i = blockIdx.x*blockDim.x + threadIdx.x; i < total; i += gridDim.x*blockDim.x) {
        if (i < N_in) {
            int e = i / (384*DTOK); int r = i % (384*DTOK);
            int c = r / DTOK, k = r % DTOK;
            g_win_h[e*(384*DTOK) + k*384 + c] = __float2half_rn(w_in[i]);
        } else if (i < N_in + N_out) {
            int j = i - N_in;
            int e = j / (DTOK*DTOK); int r = j % (DTOK*DTOK);
            int c = r / DTOK, k = r % DTOK;
            g_wout_h[e*(DTOK*DTOK) + k*DTOK + c] = __float2half_rn(w_out[j]);
        } else if (i < N_in + N_out + N_w1) {
            int j = i - N_in - N_out;
            int e = j / (FF*DTOK); int r = j % (FF*DTOK);
            int f = r / DTOK, k = r % DTOK;
            g_w1_h[e*(FF*DTOK) + k*FF + f] = __float2half_rn(w1[j]);
        } else if (i < N_in + N_out + N_w1 + N_w2) {
            int j = i - N_in - N_out - N_w1;
            int e = j / (DTOK*FF); int r = j % (DTOK*FF);
            int d = r / FF, k = r % FF;
            g_w2_h[e*(DTOK*FF) + k*DTOK + d] = __float2half_rn(w2[j]);
        } else {
            int j = i - N_in - N_out - N_w1 - N_w2;
            int c = j / 4096, k = j % 4096;
            g_h1_h[k*HH + c] = __float2half_rn(hw1[j]);
        }
    }
}

// ---------------- gating ----------------
__global__ void gating_kernel(const float* __restrict__ z, const float* __restrict__ a,
                              const float* __restrict__ wg, float* __restrict__ gates_out) {
    int b = blockIdx.x;
    int tid = threadIdx.x, w = tid >> 5, lane = tid & 31;
    __shared__ float lg[NEXP];
    float s = 0.f;
    for (int i = lane; i < 4096; i += 32) {
        int n = i >> 7, d = i & 127;
        float xv = (d < 96) ? z[(b*NA + n)*96 + d] : a[(b*NA + n)*32 + d - 96];
        s += xv * wg[i*NEXP + w];
    }
    #pragma unroll
    for (int o = 16; o; o >>= 1) s += __shfl_xor_sync(0xffffffffu, s, o);
    if (lane == 0) lg[w] = s;
    __syncthreads();
    if (tid == 0) {
        int i0 = 0; float v0 = lg[0];
        for (int e = 1; e < NEXP; e++) if (lg[e] > v0) { v0 = lg[e]; i0 = e; }
        int i1 = -1; float v1 = -1e30f;
        for (int e = 0; e < NEXP; e++) if (e != i0 && lg[e] > v1) { v1 = lg[e]; i1 = e; }
        float g0 = 1.f/(1.f + __expf(v1 - v0));
        float g1 = 1.f - g0;
        for (int e = 0; e < NEXP; e++)
            gates_out[b*NEXP + e] = (e == i0) ? g0 : ((e == i1) ? g1 : 0.f);
        g_assign[b] = make_float4((float)i0, g0, (float)i1, g1);
        float se = 0.f;
        for (int e = 0; e < NEXP; e++) se += __expf(lg[e] - v0);
        g_lse[b] = v0 + logf(se);
    }
}

// ---------------- scheduling: groups of 4 ----------------
__global__ void sched_kernel() {
    __shared__ int cnt[NEXP];
    int tid = threadIdx.x;
    if (tid < NEXP) cnt[tid] = 0;
    __syncthreads();
    for (int idx = tid; idx < 2*NB; idx += blockDim.x) {
        int b = idx >> 1, slot = idx & 1;
        float4 as = g_assign[b];
        int e = slot ? (int)as.z : (int)as.x;
        float g = slot ? as.w : as.y;
        int pos = atomicAdd(&cnt[e], 1);
        g_el_bs[e*2048 + pos] = b | (slot << 16);
        g_el_g [e*2048 + pos] = g;
    }
    __syncthreads();
    if (tid == 0) {
        int gi = 0;
        for (int e = 0; e < NEXP; e++)
            for (int s = 0; s < cnt[e]; s += 4) {
                int n = cnt[e] - s; if (n > 4) n = 4;
                g_grp[gi++] = make_int4(e, e*2048 + s, n, 0);
            }
        while (gi < MAXG) g_grp[gi++] = make_int4(-1, 0, 0, 0);
    }
}

// ---------------- balance loss ----------------
__device__ __forceinline__ float cv2_of8(const float* v) {
    float m = 0.f;
    for (int i = 0; i < 8; i++) m += v[i];
    m *= 0.125f;
    float q = 0.f;
    for (int i = 0; i < 8; i++) { float d = v[i]-m; q += d*d; }
    return (q / 7.f) / (m*m + 1e-10f);
}
__global__ void loss_kernel(const float* __restrict__ gates, float* __restrict__ out) {
    __shared__ float imp[NEXP], ldv[NEXP], red[256];
    int tid = threadIdx.x, w = tid >> 5, lane = tid & 31;
    float s = 0.f, c = 0.f;
    for (int b = lane; b < NB; b += 32) {
        float gv = gates[b*NEXP + w];
        s += gv; if (gv > 0.f) c += 1.f;
    }
    #pragma unroll
    for (int o = 16; o; o >>= 1) {
        s += __shfl_xor_sync(0xffffffffu, s, o);
        c += __shfl_xor_sync(0xffffffffu, c, o);
    }
    if (lane == 0) { imp[w] = s; ldv[w] = c; }
    float ls = 0.f;
    for (int b = tid; b < NB; b += 256) ls += g_lse[b];
    red[tid] = ls; __syncthreads();
    for (int o = 128; o; o >>= 1) { if (tid < o) red[tid] += red[tid+o]; __syncthreads(); }
    if (tid == 0)
        out[12288] = cv2_of8(imp) + cv2_of8(ldv) + red[0]*(1.f/1024.f);
}

// ---------------- staging ----------------
__device__ __forceinline__ void stage64_async(__half* buf, const __half* __restrict__ sh,
                                              int ldsrc, int c0) {
    for (int i = threadIdx.x; i < 1024; i += NT) {
        int r = i >> 3, v = i & 7;
        cpa16(buf + r*72 + v*8, sh + (size_t)r*ldsrc + c0 + v*8);
    }
    CP_COMMIT();
}
__device__ __forceinline__ void stageW2_async(__half* buf, int e, int ch) {
    const __half* sh = g_w2_h + e*131072 + (size_t)ch*64*128;
    for (int i = threadIdx.x; i < 1024; i += NT) {
        int r = i >> 4, v = i & 15;
        cpa16(buf + r*136 + v*8, sh + (size_t)r*128 + v*8);
    }
    CP_COMMIT();
}

// ---------------- GEMM helpers (8 warps, M=128, 1-pass fp16) ----------------
// C[128x64] = A[128x128] @ B[128x64]
__device__ __forceinline__ void gemm128(const __half* AHs, const __half* BHs, float* CB) {
    int w = threadIdx.x >> 5;
    int m0 = (w >> 1) << 5;     // 0,32,64,96
    int n0 = (w & 1) << 5;      // 0,32
    HC c00, c01, c10, c11;
    wmma::fill_fragment(c00, 0.f); wmma::fill_fragment(c01, 0.f);
    wmma::fill_fragment(c10, 0.f); wmma::fill_fragment(c11, 0.f);
    #pragma unroll 2
    for (int k = 0; k < 128; k += 16) {
        HA a0, a1;
        wmma::load_matrix_sync(a0, AHs + m0*136 + k, 136);
        wmma::load_matrix_sync(a1, AHs + (m0+16)*136 + k, 136);
        HB b0, b1;
        wmma::load_matrix_sync(b0, BHs + k*72 + n0, 72);
        wmma::load_matrix_sync(b1, BHs + k*72 + n0 + 16, 72);
        wmma::mma_sync(c00, a0, b0, c00); wmma::mma_sync(c01, a0, b1, c01);
        wmma::mma_sync(c10, a1, b0, c10); wmma::mma_sync(c11, a1, b1, c11);
    }
    wmma::store_matrix_sync(CB + m0*68 + n0,           c00, 68, wmma::mem_row_major);
    wmma::store_matrix_sync(CB + m0*68 + n0 + 16,      c01, 68, wmma::mem_row_major);
    wmma::store_matrix_sync(CB + (m0+16)*68 + n0,      c10, 68, wmma::mem_row_major);
    wmma::store_matrix_sync(CB + (m0+16)*68 + n0 + 16, c11, 68, wmma::mem_row_major);
}
// ff[2][4] += act[128x64] @ W2chunk[64x128]   (warp: 32 rows x 64 cols)
__device__ __forceinline__ void ffn2_acc(const __half* A2H, const __half* BHs,
                                         HC ff[2][4], int m0, int n0) {
    #pragma unroll
    for (int k = 0; k < 64; k += 16) {
        HA a0, a1;
        wmma::load_matrix_sync(a0, A2H + m0*72 + k, 72);
        wmma::load_matrix_sync(a1, A2H + (m0+16)*72 + k, 72);
        #pragma unroll
        for (int j = 0; j < 4; j++) {
            HB bh;
            wmma::load_matrix_sync(bh, BHs + k*136 + n0 + 16*j, 136);
            wmma::mma_sync(ff[0][j], a0, bh, ff[0][j]);
            wmma::mma_sync(ff[1][j], a1, bh, ff[1][j]);
        }
    }
}

// ---------------- expert kernel: one block = expert x 4 (b,slot) ----------------
__global__ void __launch_bounds__(NT, 2)
expert_kernel(const float* __restrict__ z, const float* __restrict__ a,
              const float* __restrict__ b_in, const float* __restrict__ b_out,
              const float* __restrict__ ln1g, const float* __restrict__ ln1b,
              const float* __restrict__ b1, const float* __restrict__ b2,
              const float* __restrict__ ln2g, const float* __restrict__ ln2b) {
    extern __shared__ char sm8[];
    __half* AH  = (__half*)(sm8 + OFF_AH);
    __half* B0  = (__half*)(sm8 + OFF_B0);
    __half* B1  = (__half*)(sm8 + OFF_B1);
    __half* A2H = (__half*)(sm8 + OFF_A2H);
    float*  CB  = (float*)(sm8 + OFF_A2H);   // alias (rd-to-regs then wr)
    float*  SC  = (float*)(sm8 + OFF_B0);    // scores alias over B0+B1

    int tid = threadIdx.x, w = tid >> 5, lane = tid & 31;
    int4 grp = g_grp[blockIdx.x];
    int e = grp.x;
    if (e < 0) return;

    __shared__ int s_b[4], s_slot[4];
    __shared__ float s_g[4];
    if (tid < 4) {
        if (tid < grp.z) {
            int v = g_el_bs[grp.y + tid];
            s_b[tid] = v & 0xffff; s_slot[tid] = v >> 16;
            s_g[tid] = g_el_g[grp.y + tid];
        } else { s_b[tid] = -1; s_slot[tid] = 0; s_g[tid] = 0.f; }
    }
    float* scr = g_scr + (size_t)blockIdx.x * 49152;
    const __half* winh = g_win_h + e*49152;

    stage64_async(B0, winh, 384, 0);   // qkv tile 0
    __syncthreads();                    // s_b visible

    // ---- P1: x -> AH ----
    for (int i = tid; i < 16384; i += NT) {
        int r = i >> 7, c = i & 127;
        int b = s_b[r >> 5], tok = r & 31;
        float v = 0.f;
        if (b >= 0) v = (c < 96) ? z[(b*NA + tok)*96 + c] : a[(b*NA + tok)*32 + c - 96];
        AH[r*136 + c] = __float2half_rn(v);
    }
    __syncthreads();

    // ---- P2: qkv = x @ w_in.T + b_in -> scr (double-buffered B) ----
    #pragma unroll 1
    for (int p = 0; p < 6; p++) {
        __half* bc = (p & 1) ? B1 : B0;
        if (p < 5) stage64_async((p & 1) ? B0 : B1, winh, 384, (p+1)*64);
        if (p < 5) { CP_WAIT1(); } else { CP_WAIT0(); }
        __syncthreads();
        gemm128(AH, bc, CB);
        __syncthreads();
        for (int i = tid; i < 8192; i += NT) {
            int r = i >> 6, c = i & 63;
            scr[r*384 + p*64 + c] = CB[r*68 + c] + b_in[e*384 + p*64 + c];
        }
        __syncthreads();
    }

    // ---- P3: attention, two halves (scores fit over B0+B1) ----
    #pragma unroll 1
    for (int hf = 0; hf < 2; hf++) {
        for (int idx = tid; idx < 8192; idx += NT) {
            int j = idx & 31, i = (idx >> 5) & 31, h = (idx >> 10) & 3, qq = idx >> 12;
            int qb = hf*2 + qq;
            const float4* qp = (const float4*)(scr + (qb*32+i)*384 + h*32);
            const float4* kp = (const float4*)(scr + (qb*32+j)*384 + 128 + h*32);
            float s = 0.f;
            #pragma unroll
            for (int d = 0; d < 8; d++) {
                float4 qa = qp[d], ka = kp[d];
                s += qa.x*ka.x + qa.y*ka.y + qa.z*ka.z + qa.w*ka.w;
            }
            SC[((qq*4+h)*32 + i)*33 + j] = s * 0.17677669529663687f;
        }
        __syncthreads();
        {
            float* row = SC + tid*33;   // 256 rows = 2 qb x 4 h x 32 i
            float m = row[0];
            #pragma unroll
            for (int j = 1; j < 32; j++) m = fmaxf(m, row[j]);
            float ss = 0.f;
            #pragma unroll
            for (int j = 0; j < 32; j++) { float ev = __expf(row[j]-m); row[j] = ev; ss += ev; }
            float inv = 1.f/ss;
            #pragma unroll
            for (int j = 0; j < 32; j++) row[j] *= inv;
        }
        __syncthreads();
        for (int t = tid; t < 2048; t += NT) {
            int r = t >> 5, c = (t & 31)*4;
            int qq = r >> 5, i = r & 31, h = c >> 5;
            int qb = hf*2 + qq;
            const float* pr = SC + ((qq*4+h)*32 + i)*33;
            float4 acc = make_float4(0.f,0.f,0.f,0.f);
            #pragma unroll
            for (int j = 0; j < 32; j++) {
                float p = pr[j];
                float4 vv = *(const float4*)(scr + (qb*32+j)*384 + 256 + c);
                acc.x += p*vv.x; acc.y += p*vv.y; acc.z += p*vv.z; acc.w += p*vv.w;
            }
            int rr = qb*32 + i;
            AH[rr*136+c]   = __float2half_rn(acc.x);
            AH[rr*136+c+1] = __float2half_rn(acc.y);
            AH[rr*136+c+2] = __float2half_rn(acc.z);
            AH[rr*136+c+3] = __float2half_rn(acc.w);
        }
        __syncthreads();
    }

    // ---- P4: o = attn @ w_out.T -> scr cols 0..127; prefetch W1_0/W2_0 ----
    const __half* wouth = g_wout_h + e*16384;
    stage64_async(B0, wouth, 128, 0);    // G1
    stage64_async(B1, wouth, 128, 64);   // G2
    CP_WAIT1(); __syncthreads();         // G1 done
    gemm128(AH, B0, CB);
    __syncthreads();
    stage64_async(B0, g_w1_h + e*131072, 1024, 0);   // G3 = W1_0
    for (int i = tid; i < 8192; i += NT) {
        int r = i >> 6, c = i & 63;
        scr[r*384 + c] = CB[r*68 + c];
    }
    CP_WAIT1(); __syncthreads();         // G2 done
    gemm128(AH, B1, CB);
    __syncthreads();
    stageW2_async(B1, e, 0);             // G4 = W2_0
    for (int i = tid; i < 8192; i += NT) {
        int r = i >> 6, c = i & 63;
        scr[r*384 + 64 + c] = CB[r*68 + c];
    }
    __syncthreads();

    // ---- P5: h = LN1(x + o + b_out) -> scr 128.. + AH ----
    {
        float4 gv = *(const float4*)(ln1g + e*128 + lane*4);
        float4 bv = *(const float4*)(ln1b + e*128 + lane*4);
        float4 bo = *(const float4*)(b_out + e*128 + lane*4);
        for (int rr = 0; rr < 16; rr++) {
            int r = w*16 + rr, qb = r >> 5, tok = r & 31, b = s_b[qb];
            float4 o4 = *(const float4*)(scr + r*384 + lane*4);
            float4 x4 = make_float4(0.f,0.f,0.f,0.f);
            if (b >= 0) {
                int c = lane*4;
                x4 = (c < 96) ? *(const float4*)(z + (b*NA+tok)*96 + c)
                              : *(const float4*)(a + (b*NA+tok)*32 + c - 96);
            }
            float vx = x4.x+o4.x+bo.x, vy = x4.y+o4.y+bo.y;
            float vz = x4.z+o4.z+bo.z, vw = x4.w+o4.w+bo.w;
            float s = vx+vy+vz+vw;
            #pragma unroll
            for (int o = 16; o; o >>= 1) s += __shfl_xor_sync(0xffffffffu, s, o);
            float mu = s*(1.f/128.f);
            float dx = vx-mu, dy = vy-mu, dz = vz-mu, dw = vw-mu;
            float q = dx*dx+dy*dy+dz*dz+dw*dw;
            #pragma unroll
            for (int o = 16; o; o >>= 1) q += __shfl_xor_sync(0xffffffffu, q, o);
            float rs = rsqrtf(q*(1.f/128.f) + 1e-5f);
            float hx = dx*rs*gv.x + bv.x, hy = dy*rs*gv.y + bv.y;
            float hz = dz*rs*gv.z + bv.z, hw2 = dw*rs*gv.w + bv.w;
            *(float4*)(scr + r*384 + 128 + lane*4) = make_float4(hx, hy, hz, hw2);
            int c = lane*4;
            AH[r*136+c]   = __float2half_rn(hx);
            AH[r*136+c+1] = __float2half_rn(hy);
            AH[r*136+c+2] = __float2half_rn(hz);
            AH[r*136+c+3] = __float2half_rn(hw2);
        }
    }
    __syncthreads();

    // ---- P6: FFN, pending [W1_ch(B0), W2_ch(B1)], f acc in registers ----
    int m0 = (w >> 1) << 5, n0ff = (w & 1) << 6;
    HC ff[2][4];
    #pragma unroll
    for (int i = 0; i < 2; i++)
        #pragma unroll
        for (int j = 0; j < 4; j++) wmma::fill_fragment(ff[i][j], 0.f);

    #pragma unroll 1
    for (int ch = 0; ch < 16; ch++) {
        CP_WAIT1(); __syncthreads();            // W1_ch (B0) ready
        gemm128(AH, B0, CB);
        __syncthreads();                         // B0 free, CB ready
        if (ch < 15) stage64_async(B0, g_w1_h + e*131072, 1024, (ch+1)*64);
        // act convert, phase A: rows 0..63 (CB bytes < 17408; A2H writes < 9216)
        {
            float tv[16];
            #pragma unroll
            for (int r = 0; r < 16; r++) {
                int i = tid + r*256;
                tv[r] = CB[(i >> 6)*68 + (i & 63)];
            }
            __syncthreads();
            #pragma unroll
            for (int r = 0; r < 16; r++) {
                int i = tid + r*256;
                float v = fmaxf(tv[r] + b1[e*1024 + ch*64 + (i & 63)], 0.f);
                A2H[(i >> 6)*72 + (i & 63)] = __float2half_rn(v);
            }
        }
        __syncthreads();
        // phase B: rows 64..127
        {
            float tv[16];
            #pragma unroll
            for (int r = 0; r < 16; r++) {
                int i = 4096 + tid + r*256;
                tv[r] = CB[(i >> 6)*68 + (i & 63)];
            }
            __syncthreads();
            #pragma unroll
            for (int r = 0; r < 16; r++) {
                int i = 4096 + tid + r*256;
                float v = fmaxf(tv[r] + b1[e*1024 + ch*64 + (i & 63)], 0.f);
                A2H[(i >> 6)*72 + (i & 63)] = __float2half_rn(v);
            }
        }
        if (ch < 15) { CP_WAIT1(); } else { CP_WAIT0(); }
        __syncthreads();                         // W2_ch (B1) ready + A2 visible
        ffn2_acc(A2H, B1, ff, m0, n0ff);
        __syncthreads();
        if (ch < 15) stageW2_async(B1, e, ch+1);
    }
    #pragma unroll
    for (int i = 0; i < 2; i++)
        #pragma unroll
        for (int j = 0; j < 4; j++)
            wmma::store_matrix_sync(scr + (size_t)(m0 + 16*i)*384 + 256 + n0ff + 16*j,
                                    ff[i][j], 384, wmma::mem_row_major);
    __syncthreads();

    // ---- P7: y = gate * LN2(h + f + b2) ----
    {
        float4 gv = *(const float4*)(ln2g + e*128 + lane*4);
        float4 bv = *(const float4*)(ln2b + e*128 + lane*4);
        float4 b2v = *(const float4*)(b2 + e*128 + lane*4);
        for (int rr = 0; rr < 16; rr++) {
            int r = w*16 + rr, qb = r >> 5, tok = r & 31, b = s_b[qb];
            if (b < 0) continue;
            float4 h4 = *(const float4*)(scr + r*384 + 128 + lane*4);
            float4 f4 = *(const float4*)(scr + r*384 + 256 + lane*4);
            float vx = h4.x+f4.x+b2v.x, vy = h4.y+f4.y+b2v.y;
            float vz = h4.z+f4.z+b2v.z, vw = h4.w+f4.w+b2v.w;
            float s = vx+vy+vz+vw;
            #pragma unroll
            for (int o = 16; o; o >>= 1) s += __shfl_xor_sync(0xffffffffu, s, o);
            float mu = s*(1.f/128.f);
            float dx = vx-mu, dy = vy-mu, dz = vz-mu, dw = vw-mu;
            float q = dx*dx+dy*dy+dz*dz+dw*dw;
            #pragma unroll
            for (int o = 16; o; o >>= 1) q += __shfl_xor_sync(0xffffffffu, q, o);
            float rs = rsqrtf(q*(1.f/128.f) + 1e-5f);
            float gt = s_g[qb];
            float4 res;
            res.x = (dx*rs*gv.x + bv.x)*gt; res.y = (dy*rs*gv.y + bv.y)*gt;
            res.z = (dz*rs*gv.z + bv.z)*gt; res.w = (dw*rs*gv.w + bv.w)*gt;
            *(float4*)(g_ys + ((size_t)(s_slot[qb]*NB + b))*4096 + tok*128 + lane*4) = res;
        }
    }
}

// ---------------- head1: M=32 tiles, 128 blocks, 1-pass ----------------
__global__ void __launch_bounds__(256)
head1_kernel(const float* __restrict__ hb1) {
    extern __shared__ char h1sm[];
    __half* XH = (__half*)(h1sm + H1_XH);    // 32x72
    __half* WH = (__half*)(h1sm + H1_WH);    // 64x136
    int tid = threadIdx.x, w = tid >> 5;
    int rowbase = blockIdx.x * 32;
    int colbase = blockIdx.y * 128;
    int m0 = (w >> 2) << 4;    // 0,16
    int n0 = (w & 3) << 5;     // 0..96
    HC c0, c1;
    wmma::fill_fragment(c0, 0.f);
    wmma::fill_fragment(c1, 0.f);

    for (int kc = 0; kc < 4096; kc += 64) {
        for (int i = tid; i < 1024; i += 256) {
            int r = i >> 4, v8 = i & 15;
            cpa16(WH + r*136 + v8*8, g_h1_h + (size_t)(kc + r)*HH + colbase + v8*8);
        }
        CP_COMMIT();
        for (int i = tid; i < 2048; i += 256) {
            int r = i >> 6, cc = i & 63;
            size_t gi = (size_t)(rowbase + r)*4096 + kc + cc;
            float v = g_ys[gi] + g_ys[(size_t)NB*4096 + gi];
            XH[r*72 + cc] = __float2half_rn(v);
        }
        CP_WAIT0();
        __syncthreads();
        #pragma unroll
        for (int k = 0; k < 64; k += 16) {
            HA ah;
            wmma::load_matrix_sync(ah, XH + m0*72 + k, 72);
            HB bh0, bh1;
            wmma::load_matrix_sync(bh0, WH + k*136 + n0, 136);
            wmma::load_matrix_sync(bh1, WH + k*136 + n0 + 16, 136);
            wmma::mma_sync(c0, ah, bh0, c0);
            wmma::mma_sync(c1, ah, bh1, c1);
        }
        __syncthreads();
    }
    float* OB = (float*)WH;
    wmma::store_matrix_sync(OB + m0*132 + n0,      c0, 132, wmma::mem_row_major);
    wmma::store_matrix_sync(OB + m0*132 + n0 + 16, c1, 132, wmma::mem_row_major);
    __syncthreads();
    for (int i = tid; i < 4096; i += 256) {
        int r = i >> 7, cc = i & 127;
        g_hid[(size_t)(rowbase + r)*HH + colbase + cc] =
            fmaxf(OB[r*132 + cc] + hb1[colbase + cc], 0.f);
    }
}

// ---------------- head2 ----------------
__global__ void head2_kernel(const float* __restrict__ w2h, const float* __restrict__ b2h,
                             float* __restrict__ out) {
    int b = blockIdx.x, w = threadIdx.x >> 5, lane = threadIdx.x & 31;
    const float* hp = g_hid + (size_t)b*HH;
    const float* wp = w2h + w*HH;
    float s = 0.f;
    for (int i = lane; i < HH; i += 32) s += hp[i]*wp[i];
    #pragma unroll
    for (int o = 16; o; o >>= 1) s += __shfl_xor_sync(0xffffffffu, s, o);
    if (lane == 0) out[b*NRW + w] = s + b2h[w];
}

// ---------------- launch ----------------
extern "C" void kernel_launch(void* const* d_in, const int* in_sizes, int n_in,
                              void* d_out, int out_size) {
    const float* z     = (const float*)d_in[0];
    const float* a     = (const float*)d_in[1];
    const float* w_gate= (const float*)d_in[2];
    const float* w_in  = (const float*)d_in[3];
    const float* b_in  = (const float*)d_in[4];
    const float* w_out = (const float*)d_in[5];
    const float* b_out = (const float*)d_in[6];
    const float* ln1g  = (const float*)d_in[7];
    const float* ln1b  = (const float*)d_in[8];
    const float* w1    = (const float*)d_in[9];
    const float* b1    = (const float*)d_in[10];
    const float* w2    = (const float*)d_in[11];
    const float* b2    = (const float*)d_in[12];
    const float* ln2g  = (const float*)d_in[13];
    const float* ln2b  = (const float*)d_in[14];
    const float* hw1   = (const float*)d_in[15];
    const float* hb1   = (const float*)d_in[16];
    const float* hw2   = (const float*)d_in[17];
    const float* hb2   = (const float*)d_in[18];
    float* out = (float*)d_out;

    cudaFuncSetAttribute((const void*)expert_kernel,
                         cudaFuncAttributeMaxDynamicSharedMemorySize, SMEM_BYTES);
    cudaFuncSetAttribute((const void*)head1_kernel,
                         cudaFuncAttributeMaxDynamicSharedMemorySize, H1_SMEM);

    repack_kernel<<<4096, 256>>>(w_in, w_out, w1, w2, hw1);
    gating_kernel<<<NB, 256>>>(z, a, w_gate, out + 4096);
    sched_kernel<<<1, 256>>>();
    loss_kernel<<<1, 256>>>(out + 4096, out);
    expert_kernel<<<MAXG, NT, SMEM_BYTES>>>(z, a, b_in, b_out, ln1g, ln1b,
                                            b1, b2, ln2g, ln2b);
    head1_kernel<<<dim3(32, 4), 256, H1_SMEM>>>(hb1);
    head2_kernel<<<NB, 128>>>(hw2, hb2, out);
}

// round 16
// speedup vs baseline: 1.3648x; 1.3648x over previous
#include <cuda_runtime.h>
#include <cuda_fp16.h>
#include <mma.h>
#include <math.h>

using namespace nvcuda;

#define NEXP 8
#define NB   1024
#define NA   32
#define DTOK 128
#define FF   1024
#define HH   512
#define NRW  4
#define MAXG 1032
#define NT   256

// ---------------- scratch (weights fp16, transposed) ----------------
__device__ __half g_win_h [NEXP*DTOK*384];
__device__ __half g_wout_h[NEXP*DTOK*DTOK];
__device__ __half g_w1_h  [NEXP*DTOK*FF];
__device__ __half g_w2_h  [NEXP*FF*DTOK];
__device__ __half g_h1_h  [4096*HH];

__device__ float  g_scr   [(size_t)MAXG*64*384];
__device__ float  g_ys    [2u*NB*4096];
__device__ float4 g_assign[NB];
__device__ float  g_lse   [NB];
__device__ float  g_hid   [NB*HH];
__device__ int    g_el_bs [NEXP*2048];
__device__ float  g_el_g  [NEXP*2048];
__device__ int4   g_grp   [MAXG];

// ---------------- expert smem (bytes), total 71680 -> 3 blocks/SM ----------------
#define OFF_AH   0          // 64x136 half (17408)
#define OFF_B0   17408      // 18432  (K/V fp16 during attention: K 8704 + V 8704)
#define OFF_B1   35840      // 18432
#define OFF_A2H  54272      // 64x72 half (9216); CB (64x68 fp32 = 17408) aliases 54272..71680
                            // SC2 scores (128x33 fp32 = 16896) also alias here during attention
#define SMEM_BYTES 71680

// ---------------- head1 smem (double-buffered W) ----------------
#define H1_XH    0          // 32x72 half (4608)
#define H1_W0    4608       // 64x136 half (17408); OB fp32 alias at end
#define H1_W1    (4608 + 17408)
#define H1_SMEM  (4608 + 2*17408)   // 39424

typedef wmma::fragment<wmma::matrix_a, 16,16,16, __half, wmma::row_major> HA;
typedef wmma::fragment<wmma::matrix_b, 16,16,16, __half, wmma::row_major> HB;
typedef wmma::fragment<wmma::accumulator, 16,16,16, float> HC;

__device__ __forceinline__ void cpa16(void* dst, const void* src) {
    unsigned d = (unsigned)__cvta_generic_to_shared(dst);
    asm volatile("cp.async.cg.shared.global [%0], [%1], 16;\n" :: "r"(d), "l"(src));
}
#define CP_COMMIT() asm volatile("cp.async.commit_group;\n" ::: "memory")
#define CP_WAIT0()  asm volatile("cp.async.wait_group 0;\n" ::: "memory")
#define CP_WAIT1()  asm volatile("cp.async.wait_group 1;\n" ::: "memory")

// ---------------- repack (transposed, fp16) ----------------
__global__ void repack_kernel(const float* __restrict__ w_in,
                              const float* __restrict__ w_out,
                              const float* __restrict__ w1,
                              const float* __restrict__ w2,
                              const float* __restrict__ hw1) {
    const int N_in  = NEXP*384*DTOK;
    const int N_out = NEXP*DTOK*DTOK;
    const int N_w1  = NEXP*FF*DTOK;
    const int N_w2  = NEXP*DTOK*FF;
    const int N_h1  = HH*4096;
    const int total = N_in + N_out + N_w1 + N_w2 + N_h1;
    for (int i = blockIdx.x*blockDim.x + threadIdx.x; i < total; i += gridDim.x*blockDim.x) {
        if (i < N_in) {
            int e = i / (384*DTOK); int r = i % (384*DTOK);
            int c = r / DTOK, k = r % DTOK;
            g_win_h[e*(384*DTOK) + k*384 + c] = __float2half_rn(w_in[i]);
        } else if (i < N_in + N_out) {
            int j = i - N_in;
            int e = j / (DTOK*DTOK); int r = j % (DTOK*DTOK);
            int c = r / DTOK, k = r % DTOK;
            g_wout_h[e*(DTOK*DTOK) + k*DTOK + c] = __float2half_rn(w_out[j]);
        } else if (i < N_in + N_out + N_w1) {
            int j = i - N_in - N_out;
            int e = j / (FF*DTOK); int r = j % (FF*DTOK);
            int f = r / DTOK, k = r % DTOK;
            g_w1_h[e*(FF*DTOK) + k*FF + f] = __float2half_rn(w1[j]);
        } else if (i < N_in + N_out + N_w1 + N_w2) {
            int j = i - N_in - N_out - N_w1;
            int e = j / (DTOK*FF); int r = j % (DTOK*FF);
            int d = r / FF, k = r % FF;
            g_w2_h[e*(DTOK*FF) + k*DTOK + d] = __float2half_rn(w2[j]);
        } else {
            int j = i - N_in - N_out - N_w1 - N_w2;
            int c = j / 4096, k = j % 4096;
            g_h1_h[k*HH + c] = __float2half_rn(hw1[j]);
        }
    }
}

// ---------------- gating ----------------
__global__ void gating_kernel(const float* __restrict__ z, const float* __restrict__ a,
                              const float* __restrict__ wg, float* __restrict__ gates_out) {
    int b = blockIdx.x;
    int tid = threadIdx.x, w = tid >> 5, lane = tid & 31;
    __shared__ float lg[NEXP];
    float s = 0.f;
    for (int i = lane; i < 4096; i += 32) {
        int n = i >> 7, d = i & 127;
        float xv = (d < 96) ? z[(b*NA + n)*96 + d] : a[(b*NA + n)*32 + d - 96];
        s += xv * wg[i*NEXP + w];
    }
    #pragma unroll
    for (int o = 16; o; o >>= 1) s += __shfl_xor_sync(0xffffffffu, s, o);
    if (lane == 0) lg[w] = s;
    __syncthreads();
    if (tid == 0) {
        int i0 = 0; float v0 = lg[0];
        for (int e = 1; e < NEXP; e++) if (lg[e] > v0) { v0 = lg[e]; i0 = e; }
        int i1 = -1; float v1 = -1e30f;
        for (int e = 0; e < NEXP; e++) if (e != i0 && lg[e] > v1) { v1 = lg[e]; i1 = e; }
        float g0 = 1.f/(1.f + __expf(v1 - v0));
        float g1 = 1.f - g0;
        for (int e = 0; e < NEXP; e++)
            gates_out[b*NEXP + e] = (e == i0) ? g0 : ((e == i1) ? g1 : 0.f);
        g_assign[b] = make_float4((float)i0, g0, (float)i1, g1);
        float se = 0.f;
        for (int e = 0; e < NEXP; e++) se += __expf(lg[e] - v0);
        g_lse[b] = v0 + logf(se);
    }
}

// ---------------- scheduling: groups of 2 ----------------
__global__ void sched_kernel() {
    __shared__ int cnt[NEXP];
    int tid = threadIdx.x;
    if (tid < NEXP) cnt[tid] = 0;
    __syncthreads();
    for (int idx = tid; idx < 2*NB; idx += blockDim.x) {
        int b = idx >> 1, slot = idx & 1;
        float4 as = g_assign[b];
        int e = slot ? (int)as.z : (int)as.x;
        float g = slot ? as.w : as.y;
        int pos = atomicAdd(&cnt[e], 1);
        g_el_bs[e*2048 + pos] = b | (slot << 16);
        g_el_g [e*2048 + pos] = g;
    }
    __syncthreads();
    if (tid == 0) {
        int gi = 0;
        for (int e = 0; e < NEXP; e++)
            for (int s = 0; s < cnt[e]; s += 2) {
                int n = cnt[e] - s; if (n > 2) n = 2;
                g_grp[gi++] = make_int4(e, e*2048 + s, n, 0);
            }
        while (gi < MAXG) g_grp[gi++] = make_int4(-1, 0, 0, 0);
    }
}

// ---------------- balance loss ----------------
__device__ __forceinline__ float cv2_of8(const float* v) {
    float m = 0.f;
    for (int i = 0; i < 8; i++) m += v[i];
    m *= 0.125f;
    float q = 0.f;
    for (int i = 0; i < 8; i++) { float d = v[i]-m; q += d*d; }
    return (q / 7.f) / (m*m + 1e-10f);
}
__global__ void loss_kernel(const float* __restrict__ gates, float* __restrict__ out) {
    __shared__ float imp[NEXP], ldv[NEXP], red[256];
    int tid = threadIdx.x, w = tid >> 5, lane = tid & 31;
    float s = 0.f, c = 0.f;
    for (int b = lane; b < NB; b += 32) {
        float gv = gates[b*NEXP + w];
        s += gv; if (gv > 0.f) c += 1.f;
    }
    #pragma unroll
    for (int o = 16; o; o >>= 1) {
        s += __shfl_xor_sync(0xffffffffu, s, o);
        c += __shfl_xor_sync(0xffffffffu, c, o);
    }
    if (lane == 0) { imp[w] = s; ldv[w] = c; }
    float ls = 0.f;
    for (int b = tid; b < NB; b += 256) ls += g_lse[b];
    red[tid] = ls; __syncthreads();
    for (int o = 128; o; o >>= 1) { if (tid < o) red[tid] += red[tid+o]; __syncthreads(); }
    if (tid == 0)
        out[12288] = cv2_of8(imp) + cv2_of8(ldv) + red[0]*(1.f/1024.f);
}

// ---------------- staging ----------------
__device__ __forceinline__ void stage64_async(__half* buf, const __half* __restrict__ sh,
                                              int ldsrc, int c0) {
    for (int i = threadIdx.x; i < 1024; i += NT) {
        int r = i >> 3, v = i & 7;
        cpa16(buf + r*72 + v*8, sh + (size_t)r*ldsrc + c0 + v*8);
    }
    CP_COMMIT();
}
__device__ __forceinline__ void stageW2_async(__half* buf, int e, int ch) {
    const __half* sh = g_w2_h + e*131072 + (size_t)ch*64*128;
    for (int i = threadIdx.x; i < 1024; i += NT) {
        int r = i >> 4, v = i & 15;
        cpa16(buf + r*136 + v*8, sh + (size_t)r*128 + v*8);
    }
    CP_COMMIT();
}

// ---------------- GEMM helpers (8 warps, M=64, 1-pass fp16) ----------------
__device__ __forceinline__ void gemm64(const __half* AHs, const __half* BHs, float* CB) {
    int w = threadIdx.x >> 5;
    int m0 = (w >> 1) << 4;
    int n0 = (w & 1) << 5;
    HC c0, c1;
    wmma::fill_fragment(c0, 0.f);
    wmma::fill_fragment(c1, 0.f);
    #pragma unroll 2
    for (int k = 0; k < 128; k += 16) {
        HA ah;
        wmma::load_matrix_sync(ah, AHs + m0*136 + k, 136);
        HB bh0, bh1;
        wmma::load_matrix_sync(bh0, BHs + k*72 + n0, 72);
        wmma::load_matrix_sync(bh1, BHs + k*72 + n0 + 16, 72);
        wmma::mma_sync(c0, ah, bh0, c0);
        wmma::mma_sync(c1, ah, bh1, c1);
    }
    wmma::store_matrix_sync(CB + m0*68 + n0,      c0, 68, wmma::mem_row_major);
    wmma::store_matrix_sync(CB + m0*68 + n0 + 16, c1, 68, wmma::mem_row_major);
}
__device__ __forceinline__ void ffn2_acc(const __half* A2H, const __half* BHs,
                                         HC ff[4], int m0, int n0) {
    #pragma unroll
    for (int k = 0; k < 64; k += 16) {
        HA ah;
        wmma::load_matrix_sync(ah, A2H + m0*72 + k, 72);
        #pragma unroll
        for (int j = 0; j < 4; j++) {
            HB bh;
            wmma::load_matrix_sync(bh, BHs + k*136 + n0 + 16*j, 136);
            wmma::mma_sync(ff[j], ah, bh, ff[j]);
        }
    }
}

// ---------------- expert kernel: one block = expert x 2 (b,slot) ----------------
__global__ void __launch_bounds__(NT, 3)
expert_kernel(const float* __restrict__ z, const float* __restrict__ a,
              const float* __restrict__ b_in, const float* __restrict__ b_out,
              const float* __restrict__ ln1g, const float* __restrict__ ln1b,
              const float* __restrict__ b1, const float* __restrict__ b2,
              const float* __restrict__ ln2g, const float* __restrict__ ln2b) {
    extern __shared__ char sm8[];
    __half* AH  = (__half*)(sm8 + OFF_AH);
    __half* B0  = (__half*)(sm8 + OFF_B0);
    __half* B1  = (__half*)(sm8 + OFF_B1);
    __half* A2H = (__half*)(sm8 + OFF_A2H);
    float*  CB  = (float*)(sm8 + OFF_A2H);   // gemm output / scores alias

    int tid = threadIdx.x, w = tid >> 5, lane = tid & 31;
    int4 grp = g_grp[blockIdx.x];
    int e = grp.x;
    if (e < 0) return;

    __shared__ int s_b[2], s_slot[2];
    __shared__ float s_g[2];
    if (tid < 2) {
        if (tid < grp.z) {
            int v = g_el_bs[grp.y + tid];
            s_b[tid] = v & 0xffff; s_slot[tid] = v >> 16;
            s_g[tid] = g_el_g[grp.y + tid];
        } else { s_b[tid] = -1; s_slot[tid] = 0; s_g[tid] = 0.f; }
    }
    float* scr = g_scr + (size_t)blockIdx.x * 24576;
    const __half* winh = g_win_h + e*49152;

    stage64_async(B0, winh, 384, 0);   // qkv tile 0
    __syncthreads();                    // s_b visible

    // ---- P1: x -> AH ----
    for (int i = tid; i < 8192; i += NT) {
        int r = i >> 7, c = i & 127;
        int b = s_b[r >> 5], tok = r & 31;
        float v = 0.f;
        if (b >= 0) v = (c < 96) ? z[(b*NA + tok)*96 + c] : a[(b*NA + tok)*32 + c - 96];
        AH[r*136 + c] = __float2half_rn(v);
    }
    __syncthreads();

    // ---- P2: qkv = x @ w_in.T + b_in -> scr (double-buffered B) ----
    #pragma unroll 1
    for (int p = 0; p < 6; p++) {
        __half* bc = (p & 1) ? B1 : B0;
        if (p < 5) stage64_async((p & 1) ? B0 : B1, winh, 384, (p+1)*64);
        if (p < 5) { CP_WAIT1(); } else { CP_WAIT0(); }
        __syncthreads();
        gemm64(AH, bc, CB);
        __syncthreads();
        for (int i = tid; i < 4096; i += NT) {
            int r = i >> 6, c = i & 63;
            scr[r*384 + p*64 + c] = CB[r*68 + c] + b_in[e*384 + p*64 + c];
        }
        __syncthreads();
    }

    // prefetch W_out tile 0 into B1 (idle through attention)
    const __half* wouth = g_wout_h + e*16384;
    stage64_async(B1, wouth, 128, 0);   // G1

    // ---- P3: attention, per (b,slot) pair; K/V fp16 in B0, scores in CB window ----
    #pragma unroll 1
    for (int qb = 0; qb < 2; qb++) {
        // convert K,V of this pair into B0 (K at 0, V at 4352 halfs; ld 136)
        for (int i = tid; i < 4096; i += NT) {
            int r = i >> 7, c = i & 127;
            B0[r*136 + c]        = __float2half_rn(scr[(qb*32 + r)*384 + 128 + c]);
            B0[4352 + r*136 + c] = __float2half_rn(scr[(qb*32 + r)*384 + 256 + c]);
        }
        __syncthreads();
        // scores: 128 rows (h,i) x 2 reps over j
        {
            int row = tid & 127, rep = tid >> 7;
            int h = row >> 5, i = row & 31;
            const float* qp = scr + (qb*32 + i)*384 + h*32;
            float q[32];
            #pragma unroll
            for (int d = 0; d < 32; d += 4) {
                float4 t4 = *(const float4*)(qp + d);
                q[d] = t4.x; q[d+1] = t4.y; q[d+2] = t4.z; q[d+3] = t4.w;
            }
            const __half* kb = B0 + h*32;
            #pragma unroll
            for (int jj = 0; jj < 16; jj++) {
                int j = rep*16 + jj;
                const __half2* kr = (const __half2*)(kb + j*136);
                float s = 0.f;
                #pragma unroll
                for (int d = 0; d < 16; d++) {
                    float2 kf = __half22float2(kr[d]);
                    s += q[2*d]*kf.x + q[2*d+1]*kf.y;
                }
                CB[row*33 + j] = s * 0.17677669529663687f;
            }
        }
        __syncthreads();
        if (tid < 128) {
            float* rowp = CB + tid*33;
            float m = rowp[0];
            #pragma unroll
            for (int j = 1; j < 32; j++) m = fmaxf(m, rowp[j]);
            float ss = 0.f;
            #pragma unroll
            for (int j = 0; j < 32; j++) { float ev = __expf(rowp[j]-m); rowp[j] = ev; ss += ev; }
            float inv = 1.f/ss;
            #pragma unroll
            for (int j = 0; j < 32; j++) rowp[j] *= inv;
        }
        __syncthreads();
        // attn-out -> AH rows qb*32+i
        for (int it = tid; it < 1024; it += NT) {
            int i = it & 31, c4 = it >> 5;
            int c = c4*4, h = c >> 5;
            const float* pr = CB + (h*32 + i)*33;
            const __half* vb = B0 + 4352 + c;
            float4 acc = make_float4(0.f,0.f,0.f,0.f);
            #pragma unroll
            for (int j = 0; j < 32; j++) {
                float p = pr[j];
                const __half2* vr = (const __half2*)(vb + j*136);
                float2 v0 = __half22float2(vr[0]);
                float2 v1 = __half22float2(vr[1]);
                acc.x += p*v0.x; acc.y += p*v0.y; acc.z += p*v1.x; acc.w += p*v1.y;
            }
            int rr = qb*32 + i;
            AH[rr*136+c]   = __float2half_rn(acc.x);
            AH[rr*136+c+1] = __float2half_rn(acc.y);
            AH[rr*136+c+2] = __float2half_rn(acc.z);
            AH[rr*136+c+3] = __float2half_rn(acc.w);
        }
        __syncthreads();
    }

    // ---- P4: o = attn @ w_out.T -> scr cols 0..127 ----
    stage64_async(B0, wouth, 128, 64);   // G2 (B0 free now)
    CP_WAIT1(); __syncthreads();         // G1 (B1) done
    gemm64(AH, B1, CB);
    __syncthreads();
    stage64_async(B1, g_w1_h + e*131072, 1024, 0);   // G3 = W1_0
    for (int i = tid; i < 4096; i += NT) {
        int r = i >> 6, c = i & 63;
        scr[r*384 + c] = CB[r*68 + c];
    }
    CP_WAIT1(); __syncthreads();         // G2 (B0) done
    gemm64(AH, B0, CB);
    __syncthreads();
    stageW2_async(B0, e, 0);             // G4 = W2_0
    for (int i = tid; i < 4096; i += NT) {
        int r = i >> 6, c = i & 63;
        scr[r*384 + 64 + c] = CB[r*68 + c];
    }
    __syncthreads();

    // ---- P5: h = LN1(x + o + b_out) -> scr 128.. + AH ----
    {
        float4 gv = *(const float4*)(ln1g + e*128 + lane*4);
        float4 bv = *(const float4*)(ln1b + e*128 + lane*4);
        float4 bo = *(const float4*)(b_out + e*128 + lane*4);
        for (int rr = 0; rr < 8; rr++) {
            int r = w*8 + rr, qb = r >> 5, tok = r & 31, b = s_b[qb];
            float4 o4 = *(const float4*)(scr + r*384 + lane*4);
            float4 x4 = make_float4(0.f,0.f,0.f,0.f);
            if (b >= 0) {
                int c = lane*4;
                x4 = (c < 96) ? *(const float4*)(z + (b*NA+tok)*96 + c)
                              : *(const float4*)(a + (b*NA+tok)*32 + c - 96);
            }
            float vx = x4.x+o4.x+bo.x, vy = x4.y+o4.y+bo.y;
            float vz = x4.z+o4.z+bo.z, vw = x4.w+o4.w+bo.w;
            float s = vx+vy+vz+vw;
            #pragma unroll
            for (int o = 16; o; o >>= 1) s += __shfl_xor_sync(0xffffffffu, s, o);
            float mu = s*(1.f/128.f);
            float dx = vx-mu, dy = vy-mu, dz = vz-mu, dw = vw-mu;
            float q = dx*dx+dy*dy+dz*dz+dw*dw;
            #pragma unroll
            for (int o = 16; o; o >>= 1) q += __shfl_xor_sync(0xffffffffu, q, o);
            float rs = rsqrtf(q*(1.f/128.f) + 1e-5f);
            float hx = dx*rs*gv.x + bv.x, hy = dy*rs*gv.y + bv.y;
            float hz = dz*rs*gv.z + bv.z, hw2 = dw*rs*gv.w + bv.w;
            *(float4*)(scr + r*384 + 128 + lane*4) = make_float4(hx, hy, hz, hw2);
            int c = lane*4;
            AH[r*136+c]   = __float2half_rn(hx);
            AH[r*136+c+1] = __float2half_rn(hy);
            AH[r*136+c+2] = __float2half_rn(hz);
            AH[r*136+c+3] = __float2half_rn(hw2);
        }
    }
    __syncthreads();

    // ---- P6: FFN, pending [W1_ch(B1), W2_ch(B0)], f acc in registers ----
    int m0 = (w >> 1) << 4, n0ff = (w & 1) << 6;
    HC ff[4];
    #pragma unroll
    for (int j = 0; j < 4; j++) wmma::fill_fragment(ff[j], 0.f);

    #pragma unroll 1
    for (int ch = 0; ch < 16; ch++) {
        CP_WAIT1(); __syncthreads();            // W1_ch (B1) ready
        gemm64(AH, B1, CB);
        __syncthreads();                         // B1 free, CB ready
        if (ch < 15) stage64_async(B1, g_w1_h + e*131072, 1024, (ch+1)*64);
        float tv[16];
        #pragma unroll
        for (int r = 0; r < 16; r++) {
            int i = tid + r*256;
            tv[r] = CB[(i >> 6)*68 + (i & 63)];
        }
        __syncthreads();                         // CB reads done (alias A2H)
        #pragma unroll
        for (int r = 0; r < 16; r++) {
            int i = tid + r*256;
            float v = fmaxf(tv[r] + b1[e*1024 + ch*64 + (i & 63)], 0.f);
            A2H[(i >> 6)*72 + (i & 63)] = __float2half_rn(v);
        }
        if (ch < 15) { CP_WAIT1(); } else { CP_WAIT0(); }
        __syncthreads();                         // W2_ch (B0) ready + A2 visible
        ffn2_acc(A2H, B0, ff, m0, n0ff);
        __syncthreads();
        if (ch < 15) stageW2_async(B0, e, ch+1);
    }
    #pragma unroll
    for (int j = 0; j < 4; j++)
        wmma::store_matrix_sync(scr + (size_t)m0*384 + 256 + n0ff + 16*j,
                                ff[j], 384, wmma::mem_row_major);
    __syncthreads();

    // ---- P7: y = gate * LN2(h + f + b2) ----
    {
        float4 gv = *(const float4*)(ln2g + e*128 + lane*4);
        float4 bv = *(const float4*)(ln2b + e*128 + lane*4);
        float4 b2v = *(const float4*)(b2 + e*128 + lane*4);
        for (int rr = 0; rr < 8; rr++) {
            int r = w*8 + rr, qb = r >> 5, tok = r & 31, b = s_b[qb];
            if (b < 0) continue;
            float4 h4 = *(const float4*)(scr + r*384 + 128 + lane*4);
            float4 f4 = *(const float4*)(scr + r*384 + 256 + lane*4);
            float vx = h4.x+f4.x+b2v.x, vy = h4.y+f4.y+b2v.y;
            float vz = h4.z+f4.z+b2v.z, vw = h4.w+f4.w+b2v.w;
            float s = vx+vy+vz+vw;
            #pragma unroll
            for (int o = 16; o; o >>= 1) s += __shfl_xor_sync(0xffffffffu, s, o);
            float mu = s*(1.f/128.f);
            float dx = vx-mu, dy = vy-mu, dz = vz-mu, dw = vw-mu;
            float q = dx*dx+dy*dy+dz*dz+dw*dw;
            #pragma unroll
            for (int o = 16; o; o >>= 1) q += __shfl_xor_sync(0xffffffffu, q, o);
            float rs = rsqrtf(q*(1.f/128.f) + 1e-5f);
            float gt = s_g[qb];
            float4 res;
            res.x = (dx*rs*gv.x + bv.x)*gt; res.y = (dy*rs*gv.y + bv.y)*gt;
            res.z = (dz*rs*gv.z + bv.z)*gt; res.w = (dw*rs*gv.w + bv.w)*gt;
            *(float4*)(g_ys + ((size_t)(s_slot[qb]*NB + b))*4096 + tok*128 + lane*4) = res;
        }
    }
}

// ---------------- head1: M=32 tiles, 128 blocks, double-buffered W ----------------
__global__ void __launch_bounds__(256)
head1_kernel(const float* __restrict__ hb1) {
    extern __shared__ char h1sm[];
    __half* XH = (__half*)(h1sm + H1_XH);
    __half* W0 = (__half*)(h1sm + H1_W0);
    __half* W1 = (__half*)(h1sm + H1_W1);
    int tid = threadIdx.x, w = tid >> 5;
    int rowbase = blockIdx.x * 32;
    int colbase = blockIdx.y * 128;
    int m0 = (w >> 2) << 4;
    int n0 = (w & 3) << 5;
    HC c0, c1;
    wmma::fill_fragment(c0, 0.f);
    wmma::fill_fragment(c1, 0.f);

    // prefetch W tile 0
    for (int i = tid; i < 1024; i += 256) {
        int r = i >> 4, v8 = i & 15;
        cpa16(W0 + r*136 + v8*8, g_h1_h + (size_t)r*HH + colbase + v8*8);
    }
    CP_COMMIT();

    for (int kt = 0; kt < 64; kt++) {
        int kc = kt*64;
        __half* Wc = (kt & 1) ? W1 : W0;
        __half* Wn = (kt & 1) ? W0 : W1;
        if (kt < 63) {
            for (int i = tid; i < 1024; i += 256) {
                int r = i >> 4, v8 = i & 15;
                cpa16(Wn + r*136 + v8*8, g_h1_h + (size_t)(kc + 64 + r)*HH + colbase + v8*8);
            }
            CP_COMMIT();
        }
        for (int i = tid; i < 2048; i += 256) {
            int r = i >> 6, cc = i & 63;
            size_t gi = (size_t)(rowbase + r)*4096 + kc + cc;
            float v = g_ys[gi] + g_ys[(size_t)NB*4096 + gi];
            XH[r*72 + cc] = __float2half_rn(v);
        }
        if (kt < 63) { CP_WAIT1(); } else { CP_WAIT0(); }
        __syncthreads();
        #pragma unroll
        for (int k = 0; k < 64; k += 16) {
            HA ah;
            wmma::load_matrix_sync(ah, XH + m0*72 + k, 72);
            HB bh0, bh1;
            wmma::load_matrix_sync(bh0, Wc + k*136 + n0, 136);
            wmma::load_matrix_sync(bh1, Wc + k*136 + n0 + 16, 136);
            wmma::mma_sync(c0, ah, bh0, c0);
            wmma::mma_sync(c1, ah, bh1, c1);
        }
        __syncthreads();
    }
    float* OB = (float*)W0;
    wmma::store_matrix_sync(OB + m0*132 + n0,      c0, 132, wmma::mem_row_major);
    wmma::store_matrix_sync(OB + m0*132 + n0 + 16, c1, 132, wmma::mem_row_major);
    __syncthreads();
    for (int i = tid; i < 4096; i += 256) {
        int r = i >> 7, cc = i & 127;
        g_hid[(size_t)(rowbase + r)*HH + colbase + cc] =
            fmaxf(OB[r*132 + cc] + hb1[colbase + cc], 0.f);
    }
}

// ---------------- head2 ----------------
__global__ void head2_kernel(const float* __restrict__ w2h, const float* __restrict__ b2h,
                             float* __restrict__ out) {
    int b = blockIdx.x, w = threadIdx.x >> 5, lane = threadIdx.x & 31;
    const float* hp = g_hid + (size_t)b*HH;
    const float* wp = w2h + w*HH;
    float s = 0.f;
    for (int i = lane; i < HH; i += 32) s += hp[i]*wp[i];
    #pragma unroll
    for (int o = 16; o; o >>= 1) s += __shfl_xor_sync(0xffffffffu, s, o);
    if (lane == 0) out[b*NRW + w] = s + b2h[w];
}

// ---------------- launch ----------------
extern "C" void kernel_launch(void* const* d_in, const int* in_sizes, int n_in,
                              void* d_out, int out_size) {
    const float* z     = (const float*)d_in[0];
    const float* a     = (const float*)d_in[1];
    const float* w_gate= (const float*)d_in[2];
    const float* w_in  = (const float*)d_in[3];
    const float* b_in  = (const float*)d_in[4];
    const float* w_out = (const float*)d_in[5];
    const float* b_out = (const float*)d_in[6];
    const float* ln1g  = (const float*)d_in[7];
    const float* ln1b  = (const float*)d_in[8];
    const float* w1    = (const float*)d_in[9];
    const float* b1    = (const float*)d_in[10];
    const float* w2    = (const float*)d_in[11];
    const float* b2    = (const float*)d_in[12];
    const float* ln2g  = (const float*)d_in[13];
    const float* ln2b  = (const float*)d_in[14];
    const float* hw1   = (const float*)d_in[15];
    const float* hb1   = (const float*)d_in[16];
    const float* hw2   = (const float*)d_in[17];
    const float* hb2   = (const float*)d_in[18];
    float* out = (float*)d_out;

    cudaFuncSetAttribute((const void*)expert_kernel,
                         cudaFuncAttributeMaxDynamicSharedMemorySize, SMEM_BYTES);
    cudaFuncSetAttribute((const void*)head1_kernel,
                         cudaFuncAttributeMaxDynamicSharedMemorySize, H1_SMEM);

    repack_kernel<<<4096, 256>>>(w_in, w_out, w1, w2, hw1);
    gating_kernel<<<NB, 256>>>(z, a, w_gate, out + 4096);
    sched_kernel<<<1, 256>>>();
    loss_kernel<<<1, 256>>>(out + 4096, out);
    expert_kernel<<<MAXG, NT, SMEM_BYTES>>>(z, a, b_in, b_out, ln1g, ln1b,
                                            b1, b2, ln2g, ln2b);
    head1_kernel<<<dim3(32, 4), 256, H1_SMEM>>>(hb1);
    head2_kernel<<<NB, 128>>>(hw2, hb2, out);
}